// round 1
// baseline (speedup 1.0000x reference)
#include <cuda_runtime.h>

// SCNN message passing, fp32 baseline.
// x: [B=32, C=128, H=36, W=100]; weights: [Cout=128, Cin=128, K=9]
// 4 passes, each a sequential scan: out[i] = x[i] + relu(conv1d(out[i-1])).
// Strategy: in-place on d_out; one kernel launch per scan step (graph-captured);
// weights pre-transposed to [ci][k][co] so co is contiguous (vector loads).

#define Cc   128
#define Hh   36
#define Ww   100
#define Bb   32
#define Kk   9
#define PADk 4
#define WSTRIDE 112   // smem row stride (100 + 8 halo, padded)
#define HSTRIDE 48    // smem col stride (36 + 8 halo, padded)

// Transposed weights scratch: [pass][ci*(K*C) + k*C + co]
__device__ float g_wT[4][Cc * Kk * Cc];

// ---------------------------------------------------------------------------
__global__ void transpose_w_kernel(const float* __restrict__ src, int pass) {
    int idx = blockIdx.x * blockDim.x + threadIdx.x;
    if (idx >= Cc * Cc * Kk) return;
    // src layout: [co][ci][k]
    int k  = idx % Kk;
    int ci = (idx / Kk) % Cc;
    int co = idx / (Kk * Cc);
    g_wT[pass][ci * (Kk * Cc) + k * Cc + co] = src[idx];
}

// ---------------------------------------------------------------------------
// Vertical step: out[:, :, h_cur, :] += relu( conv_W( out[:, :, h_prev, :] ) )
// grid = (16 co-blocks of 8, 32 batches), block = 128 threads (lane = w).
__global__ void __launch_bounds__(128) vstep_kernel(float* __restrict__ buf,
                                                    int pass, int h_prev, int h_cur) {
    extern __shared__ float srow[];   // [128 ci][WSTRIDE]
    const int b   = blockIdx.y;
    const int co0 = blockIdx.x * 8;
    const int tid = threadIdx.x;

    // zero the halo: positions [0..3] and [104..111] of each ci row
    for (int idx = tid; idx < Cc * 12; idx += 128) {
        int ci = idx / 12, j = idx % 12;
        int pos = (j < 4) ? j : (100 + j);   // 0..3 , 104..111
        srow[ci * WSTRIDE + pos] = 0.f;
    }
    // load prev row [128 ci][100 w] as float4 (rows are 400B => 16B aligned)
    for (int idx = tid; idx < Cc * 25; idx += 128) {
        int ci = idx / 25, j = idx % 25;
        const float4 v = *(const float4*)(buf +
            (((size_t)(b * Cc + ci)) * Hh + h_prev) * Ww + j * 4);
        *(float4*)&srow[ci * WSTRIDE + 4 + j * 4] = v;
    }
    __syncthreads();

    const int w  = tid;                       // 0..127, valid outputs: w<100
    const int wl = (w < Ww) ? w : 0;          // clamp smem window for pad lanes

    float acc[8];
#pragma unroll
    for (int j = 0; j < 8; j++) acc[j] = 0.f;

    const float* __restrict__ wp = g_wT[pass];

    for (int ci = 0; ci < Cc; ci++) {
        float win[9];
        const float* r = &srow[ci * WSTRIDE + wl];
#pragma unroll
        for (int t = 0; t < 9; t++) win[t] = r[t];   // = in[ci][w + t - 4]

        const float4* __restrict__ wrow = (const float4*)(wp + ci * (Kk * Cc) + co0);
#pragma unroll
        for (int k = 0; k < 9; k++) {
            float4 wa = __ldg(wrow + k * (Cc / 4));
            float4 wb = __ldg(wrow + k * (Cc / 4) + 1);
            float v = win[k];
            acc[0] = fmaf(wa.x, v, acc[0]);
            acc[1] = fmaf(wa.y, v, acc[1]);
            acc[2] = fmaf(wa.z, v, acc[2]);
            acc[3] = fmaf(wa.w, v, acc[3]);
            acc[4] = fmaf(wb.x, v, acc[4]);
            acc[5] = fmaf(wb.y, v, acc[5]);
            acc[6] = fmaf(wb.z, v, acc[6]);
            acc[7] = fmaf(wb.w, v, acc[7]);
        }
    }

    if (w < Ww) {
#pragma unroll
        for (int j = 0; j < 8; j++) {
            size_t o = (((size_t)(b * Cc + co0 + j)) * Hh + h_cur) * Ww + w;
            buf[o] += fmaxf(acc[j], 0.f);   // buf holds x at h_cur
        }
    }
}

// ---------------------------------------------------------------------------
// Horizontal step: out[:, :, :, w_cur] += relu( conv_H( out[:, :, :, w_prev] ) )
// grid = (16 co-blocks of 8, 32 batches), block = 144 threads = 36 h x 4 co_sub.
__global__ void __launch_bounds__(144) hstep_kernel(float* __restrict__ buf,
                                                    int pass, int w_prev, int w_cur) {
    __shared__ float scol[Cc * HSTRIDE];   // [128 ci][48]
    const int b   = blockIdx.y;
    const int co0 = blockIdx.x * 8;
    const int tid = threadIdx.x;

    // zero halo: [0..3] and [40..47]
    for (int idx = tid; idx < Cc * 12; idx += 144) {
        int ci = idx / 12, j = idx % 12;
        int pos = (j < 4) ? j : (36 + j);
        scol[ci * HSTRIDE + pos] = 0.f;
    }
    // load prev column [128 ci][36 h] (strided gather, stays L2-hot)
    for (int idx = tid; idx < Cc * Hh; idx += 144) {
        int ci = idx / Hh, h = idx % Hh;
        scol[ci * HSTRIDE + 4 + h] =
            buf[(((size_t)(b * Cc + ci)) * Hh + h) * Ww + w_prev];
    }
    __syncthreads();

    const int co_sub = tid / Hh;         // 0..3
    const int h      = tid - co_sub * Hh;
    const int co     = co0 + co_sub * 2; // NCO = 2

    float acc0 = 0.f, acc1 = 0.f;
    const float* __restrict__ wp = g_wT[pass];

    for (int ci = 0; ci < Cc; ci++) {
        float win[9];
        const float* r = &scol[ci * HSTRIDE + h];
#pragma unroll
        for (int t = 0; t < 9; t++) win[t] = r[t];   // = in[ci][h + t - 4]

        const float2* __restrict__ wrow = (const float2*)(wp + ci * (Kk * Cc) + co);
#pragma unroll
        for (int k = 0; k < 9; k++) {
            float2 wv = __ldg(wrow + k * (Cc / 2));
            acc0 = fmaf(wv.x, win[k], acc0);
            acc1 = fmaf(wv.y, win[k], acc1);
        }
    }

    {
        size_t o0 = (((size_t)(b * Cc + co)) * Hh + h) * Ww + w_cur;
        size_t o1 = (((size_t)(b * Cc + co + 1)) * Hh + h) * Ww + w_cur;
        buf[o0] += fmaxf(acc0, 0.f);
        buf[o1] += fmaxf(acc1, 0.f);
    }
}

// ---------------------------------------------------------------------------
extern "C" void kernel_launch(void* const* d_in, const int* in_sizes, int n_in,
                              void* d_out, int out_size) {
    (void)in_sizes; (void)n_in; (void)out_size;
    float* buf = (float*)d_out;
    const size_t xbytes = (size_t)Bb * Cc * Hh * Ww * sizeof(float);

    // buf <- x  (passes run in place on d_out)
    cudaMemcpyAsync(buf, d_in[0], xbytes, cudaMemcpyDeviceToDevice);

    // transpose all 4 weight tensors into g_wT
    const int nw = Cc * Cc * Kk;
    for (int p = 0; p < 4; p++) {
        transpose_w_kernel<<<(nw + 255) / 256, 256>>>((const float*)d_in[1 + p], p);
    }

    const int vsmem = Cc * WSTRIDE * (int)sizeof(float);   // 57344 B
    cudaFuncSetAttribute((const void*)vstep_kernel,
                         cudaFuncAttributeMaxDynamicSharedMemorySize, vsmem);

    dim3 grid(16, 32);

    // Pass 1: up->down (w_ud), forward over H
    for (int h = 1; h < Hh; h++)
        vstep_kernel<<<grid, 128, vsmem>>>(buf, 0, h - 1, h);

    // Pass 2: down->up (w_du), reverse over H
    for (int h = Hh - 2; h >= 0; h--)
        vstep_kernel<<<grid, 128, vsmem>>>(buf, 1, h + 1, h);

    // Pass 3: left->right (w_lr), forward over W
    for (int w = 1; w < Ww; w++)
        hstep_kernel<<<grid, 144>>>(buf, 2, w - 1, w);

    // Pass 4: right->left (w_rl), reverse over W
    for (int w = Ww - 2; w >= 0; w--)
        hstep_kernel<<<grid, 144>>>(buf, 3, w + 1, w);
}

// round 2
// speedup vs baseline: 2.8002x; 2.8002x over previous
#include <cuda_runtime.h>

// SCNN message passing, packed-f32x2 version.
// x: [B=32, C=128, H=36, W=100]; weights: [128, 128, 9]
// 4 passes: out[i] = x[i] + relu(conv1d(out[i-1])) scanned over H, H-rev, W, W-rev.
// Vertical passes run in place on d_out ([B,C,H,W], conv along W).
// Horizontal passes run on a transposed scratch [B,C,W,H] (conv along H contiguous).

#define Bb 32
#define Cc 128
#define Hh 36
#define Ww 100
#define Kk 9
#define PLANE 3600          // H*W

#define VSM_W 112           // vstep smem row stride (4 halo + 100 + 8 pad)
#define HSM_W 48            // hstep smem row stride (4 halo + 36 + 8 pad)

// Transposed weights: [pass][ci*(9*128) + k*128 + co]
__device__ float g_wT[4][Cc * Kk * Cc];
// Transposed feature scratch: [B][C][W][H]
__device__ float g_tbuf[(size_t)Bb * Cc * Ww * Hh];

// ---------------- packed f32x2 helpers ----------------
typedef unsigned long long ull;
__device__ __forceinline__ ull pk2(float x) {
    ull r; asm("mov.b64 %0, {%1, %1};" : "=l"(r) : "f"(x)); return r;
}
__device__ __forceinline__ void fma2(ull& d, ull a, ull b) {
    asm("fma.rn.f32x2 %0, %1, %2, %0;" : "+l"(d) : "l"(a), "l"(b));
}
__device__ __forceinline__ float2 unpk(ull v) {
    float2 f; asm("mov.b64 {%0, %1}, %2;" : "=f"(f.x), "=f"(f.y) : "l"(v)); return f;
}

// ---------------------------------------------------------------------------
__global__ void transpose_w_kernel(const float* __restrict__ src, int pass) {
    int idx = blockIdx.x * blockDim.x + threadIdx.x;
    if (idx >= Cc * Cc * Kk) return;
    int k  = idx % Kk;
    int ci = (idx / Kk) % Cc;
    int co = idx / (Kk * Cc);
    g_wT[pass][ci * (Kk * Cc) + k * Cc + co] = src[idx];
}

// ---------------------------------------------------------------------------
// Vertical step on buf [B,C,H,W]: row h_cur += relu(convW(row h_prev)).
// grid (8 co-blocks of 16, 32 b), block 224 (200 active: 25 wq x 8 co-pairs).
// smem: srow[128][112] + wsm[128*9][16]  = 131072 B.
__global__ void __launch_bounds__(224) vstep_kernel(float* __restrict__ buf,
                                                    int pass, int h_prev, int h_cur) {
    extern __shared__ float sm[];
    float* srow = sm;                     // [128][VSM_W]
    float* wsm  = sm + Cc * VSM_W;        // [128*9][16]

    const int b   = blockIdx.y;
    const int co0 = blockIdx.x * 16;
    const int tid = threadIdx.x;

    // halo zero: pos 0..3 and 104..111 per ci
    for (int i = tid; i < Cc * 12; i += 224) {
        int ci = i / 12, j = i % 12;
        int pos = (j < 4) ? j : (100 + j);
        srow[ci * VSM_W + pos] = 0.f;
    }
    // prev row: 128 x 100 floats, contiguous per ci
    {
        const float* src = buf + (size_t)(b * Cc) * PLANE + (size_t)h_prev * Ww;
        for (int i = tid; i < Cc * 25; i += 224) {
            int ci = i / 25, q = i % 25;
            float4 v = *(const float4*)(src + (size_t)ci * PLANE + q * 4);
            *(float4*)&srow[ci * VSM_W + 4 + q * 4] = v;
        }
    }
    // weight slice: [128ci][9k][16co]  (4608 float4)
    {
        const float* wsrc = g_wT[pass];
        for (int i = tid; i < Cc * Kk * 4; i += 224) {
            int rk = i >> 2, q = (i & 3) * 4;
            *(float4*)&wsm[rk * 16 + q] = *(const float4*)(wsrc + rk * Cc + co0 + q);
        }
    }
    __syncthreads();

    if (tid < 200) {
        const int wq = tid % 25;      // 4 w per thread
        const int cp = tid / 25;      // 0..7 co-pair
        const int w0 = wq * 4;

        ull acc0 = 0, acc1 = 0, acc2 = 0, acc3 = 0;

        for (int ci = 0; ci < Cc; ci++) {
            const float* r = &srow[ci * VSM_W + w0];
            float4 a = *(const float4*)(r);
            float4 bq = *(const float4*)(r + 4);
            float4 c = *(const float4*)(r + 8);
            ull wv[12];
            wv[0] = pk2(a.x);  wv[1] = pk2(a.y);  wv[2]  = pk2(a.z);  wv[3]  = pk2(a.w);
            wv[4] = pk2(bq.x); wv[5] = pk2(bq.y); wv[6]  = pk2(bq.z); wv[7]  = pk2(bq.w);
            wv[8] = pk2(c.x);  wv[9] = pk2(c.y);  wv[10] = pk2(c.z);  wv[11] = pk2(c.w);

            const float* wp = &wsm[ci * (Kk * 16) + cp * 2];
#pragma unroll
            for (int k = 0; k < Kk; k++) {
                ull wt = *(const ull*)(wp + k * 16);
                fma2(acc0, wv[k + 0], wt);
                fma2(acc1, wv[k + 1], wt);
                fma2(acc2, wv[k + 2], wt);
                fma2(acc3, wv[k + 3], wt);
            }
        }

        const int co = co0 + cp * 2;
        float2 r0 = unpk(acc0), r1 = unpk(acc1), r2 = unpk(acc2), r3 = unpk(acc3);
        size_t base = ((size_t)(b * Cc + co) * Hh + h_cur) * Ww + w0;
        float4 p = *(float4*)(buf + base);
        p.x += fmaxf(r0.x, 0.f); p.y += fmaxf(r1.x, 0.f);
        p.z += fmaxf(r2.x, 0.f); p.w += fmaxf(r3.x, 0.f);
        *(float4*)(buf + base) = p;
        float4 q = *(float4*)(buf + base + PLANE);
        q.x += fmaxf(r0.y, 0.f); q.y += fmaxf(r1.y, 0.f);
        q.z += fmaxf(r2.y, 0.f); q.w += fmaxf(r3.y, 0.f);
        *(float4*)(buf + base + PLANE) = q;
    }
}

// ---------------------------------------------------------------------------
// Horizontal step on g_tbuf [B,C,W,H]: col w_cur += relu(convH(col w_prev)).
// grid (8 co-blocks of 16, 32 b), block 160 (144 active: 18 hq x 8 co-pairs).
// smem: srow[128][48] + wsm[128*9][16] = 98304 B.
__global__ void __launch_bounds__(160) hstep_kernel(int pass, int w_prev, int w_cur) {
    extern __shared__ float sm[];
    float* srow = sm;                     // [128][HSM_W]
    float* wsm  = sm + Cc * HSM_W;

    const int b   = blockIdx.y;
    const int co0 = blockIdx.x * 16;
    const int tid = threadIdx.x;
    float* tbuf = g_tbuf;

    for (int i = tid; i < Cc * 12; i += 160) {
        int ci = i / 12, j = i % 12;
        int pos = (j < 4) ? j : (36 + j);
        srow[ci * HSM_W + pos] = 0.f;
    }
    {
        const float* src = tbuf + (size_t)(b * Cc) * PLANE + (size_t)w_prev * Hh;
        for (int i = tid; i < Cc * 9; i += 160) {
            int ci = i / 9, q = i % 9;
            float4 v = *(const float4*)(src + (size_t)ci * PLANE + q * 4);
            *(float4*)&srow[ci * HSM_W + 4 + q * 4] = v;
        }
    }
    {
        const float* wsrc = g_wT[pass];
        for (int i = tid; i < Cc * Kk * 4; i += 160) {
            int rk = i >> 2, q = (i & 3) * 4;
            *(float4*)&wsm[rk * 16 + q] = *(const float4*)(wsrc + rk * Cc + co0 + q);
        }
    }
    __syncthreads();

    if (tid < 144) {
        const int hq = tid % 18;      // 2 h per thread
        const int cp = tid / 18;      // 0..7
        const int h0 = hq * 2;

        ull acc0 = 0, acc1 = 0;

        for (int ci = 0; ci < Cc; ci++) {
            const float* r = &srow[ci * HSM_W + h0];
            ull wv[10];
#pragma unroll
            for (int t = 0; t < 10; t++) wv[t] = pk2(r[t]);

            const float* wp = &wsm[ci * (Kk * 16) + cp * 2];
#pragma unroll
            for (int k = 0; k < Kk; k++) {
                ull wt = *(const ull*)(wp + k * 16);
                fma2(acc0, wv[k + 0], wt);
                fma2(acc1, wv[k + 1], wt);
            }
        }

        const int co = co0 + cp * 2;
        float2 r0 = unpk(acc0), r1 = unpk(acc1);
        size_t base = ((size_t)(b * Cc + co) * Ww + w_cur) * Hh + h0;
        float2 p = *(float2*)(tbuf + base);
        p.x += fmaxf(r0.x, 0.f); p.y += fmaxf(r1.x, 0.f);
        *(float2*)(tbuf + base) = p;
        float2 q = *(float2*)(tbuf + base + PLANE);
        q.x += fmaxf(r0.y, 0.f); q.y += fmaxf(r1.y, 0.f);
        *(float2*)(tbuf + base + PLANE) = q;
    }
}

// ---------------------------------------------------------------------------
// Transposes between buf [.,H,W] and g_tbuf [.,W,H] per (b,c) plane.
__global__ void t_fwd_kernel(const float* __restrict__ src) {   // buf -> tbuf
    __shared__ float t[32][33];
    size_t p = blockIdx.z;
    const float* s = src + p * PLANE;
    float* d = g_tbuf + p * PLANE;
    int c0 = blockIdx.x * 32, r0 = blockIdx.y * 32;
#pragma unroll
    for (int j = 0; j < 4; j++) {
        int r = r0 + threadIdx.y + j * 8, c = c0 + threadIdx.x;
        if (r < Hh && c < Ww) t[threadIdx.y + j * 8][threadIdx.x] = s[r * Ww + c];
    }
    __syncthreads();
#pragma unroll
    for (int j = 0; j < 4; j++) {
        int r = c0 + threadIdx.y + j * 8, c = r0 + threadIdx.x;
        if (r < Ww && c < Hh) d[r * Hh + c] = t[threadIdx.x][threadIdx.y + j * 8];
    }
}

__global__ void t_bwd_kernel(float* __restrict__ dst) {         // tbuf -> buf
    __shared__ float t[32][33];
    size_t p = blockIdx.z;
    const float* s = g_tbuf + p * PLANE;
    float* d = dst + p * PLANE;
    int c0 = blockIdx.x * 32, r0 = blockIdx.y * 32;
#pragma unroll
    for (int j = 0; j < 4; j++) {
        int r = r0 + threadIdx.y + j * 8, c = c0 + threadIdx.x;
        if (r < Ww && c < Hh) t[threadIdx.y + j * 8][threadIdx.x] = s[r * Hh + c];
    }
    __syncthreads();
#pragma unroll
    for (int j = 0; j < 4; j++) {
        int r = c0 + threadIdx.y + j * 8, c = r0 + threadIdx.x;
        if (r < Hh && c < Ww) d[r * Ww + c] = t[threadIdx.x][threadIdx.y + j * 8];
    }
}

// ---------------------------------------------------------------------------
extern "C" void kernel_launch(void* const* d_in, const int* in_sizes, int n_in,
                              void* d_out, int out_size) {
    (void)in_sizes; (void)n_in; (void)out_size;
    float* buf = (float*)d_out;
    const size_t xbytes = (size_t)Bb * Cc * Hh * Ww * sizeof(float);

    cudaMemcpyAsync(buf, d_in[0], xbytes, cudaMemcpyDeviceToDevice);

    const int nw = Cc * Cc * Kk;
    for (int p = 0; p < 4; p++)
        transpose_w_kernel<<<(nw + 255) / 256, 256>>>((const float*)d_in[1 + p], p);

    const int vsmem = (Cc * VSM_W + Cc * Kk * 16) * (int)sizeof(float);  // 131072
    const int hsmem = (Cc * HSM_W + Cc * Kk * 16) * (int)sizeof(float);  //  98304
    cudaFuncSetAttribute((const void*)vstep_kernel,
                         cudaFuncAttributeMaxDynamicSharedMemorySize, vsmem);
    cudaFuncSetAttribute((const void*)hstep_kernel,
                         cudaFuncAttributeMaxDynamicSharedMemorySize, hsmem);

    dim3 grid(8, 32);

    // Pass 1: up->down (forward over H)
    for (int h = 1; h < Hh; h++)
        vstep_kernel<<<grid, 224, vsmem>>>(buf, 0, h - 1, h);
    // Pass 2: down->up (reverse over H)
    for (int h = Hh - 2; h >= 0; h--)
        vstep_kernel<<<grid, 224, vsmem>>>(buf, 1, h + 1, h);

    // Transpose to [B,C,W,H]
    {
        dim3 tb(32, 8), tg(4, 2, Bb * Cc);
        t_fwd_kernel<<<tg, tb>>>(buf);
    }

    // Pass 3: left->right (forward over W)
    for (int w = 1; w < Ww; w++)
        hstep_kernel<<<grid, 160, hsmem>>>(2, w - 1, w);
    // Pass 4: right->left (reverse over W)
    for (int w = Ww - 2; w >= 0; w--)
        hstep_kernel<<<grid, 160, hsmem>>>(3, w + 1, w);

    // Transpose back
    {
        dim3 tb(32, 8), tg(2, 4, Bb * Cc);
        t_bwd_kernel<<<tg, tb>>>(buf);
    }
}

// round 6
// speedup vs baseline: 4.1305x; 1.4750x over previous
#include <cuda_runtime.h>

// SCNN message passing — persistent-per-pass version.
// x: [B=32, C=128, H=36, W=100]; weights [128,128,9]; 4 passes of
// out[i] = x[i] + relu(conv1d(out[i-1])) scanned over H, H-rev, W, W-rev.
// Vertical passes in place on d_out [B,C,H,W]; horizontal passes on a
// transposed scratch [B,C,W,H]. Each pass = ONE kernel: 128 CTAs (4 co-blocks
// x 32 b), 1 CTA/SM, weights staged in smem once, steps separated by a 4-CTA
// atomic spin barrier per batch group.

#define Bb 32
#define Cc 128
#define Hh 36
#define Ww 100
#define Kk 9
#define PLANE 3600

#define VSM_W 112     // vpass smem row stride: 4 halo + 100 + 8 pad
#define HSM_W 48      // hpass smem row stride: 4 halo + 36 + 8 pad
#define COB  32       // co per CTA

typedef unsigned long long ull;

// Transposed weights: [pass][ (ci*9 + k)*128 + co ]
__device__ float g_wT[4][Cc * Kk * Cc];
// Transposed feature scratch [B][C][W][H]
__device__ float g_tbuf[(size_t)Bb * Cc * Ww * Hh];
// Spin-barrier counters: [pass][b]
__device__ unsigned g_bar[4][Bb];

__device__ __forceinline__ ull pk2(float x) {
    ull r; asm("mov.b64 %0, {%1, %1};" : "=l"(r) : "f"(x)); return r;
}
__device__ __forceinline__ void fma2(ull& d, ull a, ull b) {
    asm("fma.rn.f32x2 %0, %1, %2, %0;" : "+l"(d) : "l"(a), "l"(b));
}
__device__ __forceinline__ float2 unpk(ull v) {
    float2 f; asm("mov.b64 {%0, %1}, %2;" : "=f"(f.x), "=f"(f.y) : "l"(v)); return f;
}

// ---------------------------------------------------------------------------
__global__ void transpose_w_kernel(const float* __restrict__ src, int pass) {
    int idx = blockIdx.x * blockDim.x + threadIdx.x;
    if (pass == 0 && blockIdx.x == 0 && threadIdx.x < 4 * Bb)
        ((unsigned*)g_bar)[threadIdx.x] = 0u;     // reset barriers each replay
    if (idx >= Cc * Cc * Kk) return;
    int k  = idx % Kk;
    int ci = (idx / Kk) % Cc;
    int co = idx / (Kk * Cc);
    g_wT[pass][(ci * Kk + k) * Cc + co] = src[idx];
}

// ---------------------------------------------------------------------------
// 4-CTA group barrier (group = batch b). All threads: fence; then tid0
// arrives + spins; then block-wide release.
__device__ __forceinline__ void group_barrier(unsigned* bar, unsigned target) {
    __threadfence();
    __syncthreads();
    if (threadIdx.x == 0) {
        atomicAdd(bar, 1u);
        while (atomicAdd(bar, 0u) < target) {}
    }
    __syncthreads();
}

// ---------------------------------------------------------------------------
// Vertical pass (conv along W, scan over H), in place on buf [B,C,H,W].
// grid (4, 32); block 224 (200 compute threads: 25 wq x 8 cq).
// smem: wsm[128*9][32] (147456B) + srow[128][112] (57344B) = 204800B.
__global__ void __launch_bounds__(224) vpass_kernel(float* __restrict__ buf,
                                                    int pass, int dir) {
    extern __shared__ float sm[];
    float* wsm  = sm;                       // [ (ci*9+k) ][32 co]
    float* srow = sm + Cc * Kk * COB;       // [128 ci][VSM_W]

    const int b   = blockIdx.y;
    const int co0 = blockIdx.x * COB;
    const int tid = threadIdx.x;

    // stage weights once: 9216 float4
    for (int i = tid; i < Cc * Kk * (COB / 4); i += 224) {
        int r = i / (COB / 4), q = (i % (COB / 4)) * 4;
        *(float4*)&wsm[r * COB + q] = *(const float4*)&g_wT[pass][r * Cc + co0 + q];
    }
    // halo zero
    for (int i = tid; i < Cc * 12; i += 224) {
        int ci = i / 12, j = i % 12;
        srow[ci * VSM_W + ((j < 4) ? j : (100 + j))] = 0.f;
    }

    unsigned* bar = &g_bar[pass][b];
    const int wq = tid % 25, cq = tid / 25;    // cq 0..7 valid
    const int w0 = wq * 4;

    for (int s = 0; s < Hh - 1; s++) {
        const int h_cur  = (dir > 0) ? (1 + s) : (Hh - 2 - s);
        const int h_prev = (dir > 0) ? s       : (Hh - 1 - s);

        // stage prev row (L2-fresh)
        const float* src = buf + (size_t)(b * Cc) * PLANE + (size_t)h_prev * Ww;
        for (int i = tid; i < Cc * 25; i += 224) {
            int ci = i / 25, q = i % 25;
            float4 v = __ldcg((const float4*)(src + (size_t)ci * PLANE + q * 4));
            *(float4*)&srow[ci * VSM_W + 4 + q * 4] = v;
        }
        __syncthreads();

        if (tid < 200) {
            ull acc[8];                        // [w0..3][copair0..1]
#pragma unroll
            for (int j = 0; j < 8; j++) acc[j] = 0;

            for (int ci = 0; ci < Cc; ci++) {
                const float* r = &srow[ci * VSM_W + w0];
                float4 A = *(const float4*)(r);
                float4 B = *(const float4*)(r + 4);
                float4 C = *(const float4*)(r + 8);
                ull wv[12];
                wv[0] = pk2(A.x); wv[1] = pk2(A.y); wv[2]  = pk2(A.z); wv[3]  = pk2(A.w);
                wv[4] = pk2(B.x); wv[5] = pk2(B.y); wv[6]  = pk2(B.z); wv[7]  = pk2(B.w);
                wv[8] = pk2(C.x); wv[9] = pk2(C.y); wv[10] = pk2(C.z); wv[11] = pk2(C.w);

                const float* wb = &wsm[ci * (Kk * COB) + cq * 4];
#pragma unroll
                for (int k = 0; k < Kk; k++) {
                    ulonglong2 wt = *(const ulonglong2*)(wb + k * COB);
                    fma2(acc[0], wv[k + 0], wt.x); fma2(acc[1], wv[k + 0], wt.y);
                    fma2(acc[2], wv[k + 1], wt.x); fma2(acc[3], wv[k + 1], wt.y);
                    fma2(acc[4], wv[k + 2], wt.x); fma2(acc[5], wv[k + 2], wt.y);
                    fma2(acc[6], wv[k + 3], wt.x); fma2(acc[7], wv[k + 3], wt.y);
                }
            }

            // out[b][co0+cq*4 + j][h_cur][w0..w0+3] += relu(acc)
            float2 u0 = unpk(acc[0]), u1 = unpk(acc[2]), u2 = unpk(acc[4]), u3 = unpk(acc[6]);
            float2 v0 = unpk(acc[1]), v1 = unpk(acc[3]), v2 = unpk(acc[5]), v3 = unpk(acc[7]);
            const int co = co0 + cq * 4;
            size_t base = ((size_t)(b * Cc + co) * Hh + h_cur) * Ww + w0;
            float4 p;
            p = *(float4*)(buf + base);
            p.x += fmaxf(u0.x, 0.f); p.y += fmaxf(u1.x, 0.f);
            p.z += fmaxf(u2.x, 0.f); p.w += fmaxf(u3.x, 0.f);
            *(float4*)(buf + base) = p;
            p = *(float4*)(buf + base + PLANE);
            p.x += fmaxf(u0.y, 0.f); p.y += fmaxf(u1.y, 0.f);
            p.z += fmaxf(u2.y, 0.f); p.w += fmaxf(u3.y, 0.f);
            *(float4*)(buf + base + PLANE) = p;
            p = *(float4*)(buf + base + 2 * PLANE);
            p.x += fmaxf(v0.x, 0.f); p.y += fmaxf(v1.x, 0.f);
            p.z += fmaxf(v2.x, 0.f); p.w += fmaxf(v3.x, 0.f);
            *(float4*)(buf + base + 2 * PLANE) = p;
            p = *(float4*)(buf + base + 3 * PLANE);
            p.x += fmaxf(v0.y, 0.f); p.y += fmaxf(v1.y, 0.f);
            p.z += fmaxf(v2.y, 0.f); p.w += fmaxf(v3.y, 0.f);
            *(float4*)(buf + base + 3 * PLANE) = p;
        }

        if (s < Hh - 2) group_barrier(bar, 4u * (s + 1));
    }
}

// ---------------------------------------------------------------------------
// Horizontal pass (conv along H, scan over W) on g_tbuf [B,C,W,H].
// grid (4, 32); block 160 (144 compute threads: 18 hq x 8 cq).
// smem: wsm 147456B + scol[128][48] 24576B = 172032B.
__global__ void __launch_bounds__(160) hpass_kernel(int pass, int dir) {
    extern __shared__ float sm[];
    float* wsm  = sm;
    float* scol = sm + Cc * Kk * COB;

    const int b   = blockIdx.y;
    const int co0 = blockIdx.x * COB;
    const int tid = threadIdx.x;
    float* tbuf = g_tbuf;

    for (int i = tid; i < Cc * Kk * (COB / 4); i += 160) {
        int r = i / (COB / 4), q = (i % (COB / 4)) * 4;
        *(float4*)&wsm[r * COB + q] = *(const float4*)&g_wT[pass][r * Cc + co0 + q];
    }
    for (int i = tid; i < Cc * 12; i += 160) {
        int ci = i / 12, j = i % 12;
        scol[ci * HSM_W + ((j < 4) ? j : (36 + j))] = 0.f;
    }

    unsigned* bar = &g_bar[pass][b];
    const int hq = tid % 18, cq = tid / 18;   // cq 0..7 valid
    const int h0 = hq * 2;

    for (int s = 0; s < Ww - 1; s++) {
        const int w_cur  = (dir > 0) ? (1 + s) : (Ww - 2 - s);
        const int w_prev = (dir > 0) ? s       : (Ww - 1 - s);

        const float* src = tbuf + (size_t)(b * Cc) * PLANE + (size_t)w_prev * Hh;
        for (int i = tid; i < Cc * 9; i += 160) {
            int ci = i / 9, q = i % 9;
            float4 v = __ldcg((const float4*)(src + (size_t)ci * PLANE + q * 4));
            *(float4*)&scol[ci * HSM_W + 4 + q * 4] = v;
        }
        __syncthreads();

        if (tid < 144) {
            ull acc[4];                        // [h0,h1][copair0,1]
#pragma unroll
            for (int j = 0; j < 4; j++) acc[j] = 0;

            for (int ci = 0; ci < Cc; ci++) {
                const float* r = &scol[ci * HSM_W + h0];
                float2 d0 = *(const float2*)(r);
                float2 d1 = *(const float2*)(r + 2);
                float2 d2 = *(const float2*)(r + 4);
                float2 d3 = *(const float2*)(r + 6);
                float2 d4 = *(const float2*)(r + 8);
                ull wv[10];
                wv[0] = pk2(d0.x); wv[1] = pk2(d0.y);
                wv[2] = pk2(d1.x); wv[3] = pk2(d1.y);
                wv[4] = pk2(d2.x); wv[5] = pk2(d2.y);
                wv[6] = pk2(d3.x); wv[7] = pk2(d3.y);
                wv[8] = pk2(d4.x); wv[9] = pk2(d4.y);

                const float* wb = &wsm[ci * (Kk * COB) + cq * 4];
#pragma unroll
                for (int k = 0; k < Kk; k++) {
                    ulonglong2 wt = *(const ulonglong2*)(wb + k * COB);
                    fma2(acc[0], wv[k + 0], wt.x); fma2(acc[1], wv[k + 0], wt.y);
                    fma2(acc[2], wv[k + 1], wt.x); fma2(acc[3], wv[k + 1], wt.y);
                }
            }

            float2 a0 = unpk(acc[0]), a1 = unpk(acc[2]);   // copair0: h0, h1
            float2 b0 = unpk(acc[1]), b1 = unpk(acc[3]);   // copair1
            const int co = co0 + cq * 4;
            size_t base = ((size_t)(b * Cc + co) * Ww + w_cur) * Hh + h0;
            float2 p;
            p = *(float2*)(tbuf + base);
            p.x += fmaxf(a0.x, 0.f); p.y += fmaxf(a1.x, 0.f);
            *(float2*)(tbuf + base) = p;
            p = *(float2*)(tbuf + base + PLANE);
            p.x += fmaxf(a0.y, 0.f); p.y += fmaxf(a1.y, 0.f);
            *(float2*)(tbuf + base + PLANE) = p;
            p = *(float2*)(tbuf + base + 2 * PLANE);
            p.x += fmaxf(b0.x, 0.f); p.y += fmaxf(b1.x, 0.f);
            *(float2*)(tbuf + base + 2 * PLANE) = p;
            p = *(float2*)(tbuf + base + 3 * PLANE);
            p.x += fmaxf(b0.y, 0.f); p.y += fmaxf(b1.y, 0.f);
            *(float2*)(tbuf + base + 3 * PLANE) = p;
        }

        if (s < Ww - 2) group_barrier(bar, 4u * (s + 1));
    }
}

// ---------------------------------------------------------------------------
__global__ void t_fwd_kernel(const float* __restrict__ src) {   // buf -> tbuf
    __shared__ float t[32][33];
    size_t p = blockIdx.z;
    const float* s = src + p * PLANE;
    float* d = g_tbuf + p * PLANE;
    int c0 = blockIdx.x * 32, r0 = blockIdx.y * 32;
#pragma unroll
    for (int j = 0; j < 4; j++) {
        int r = r0 + threadIdx.y + j * 8, c = c0 + threadIdx.x;
        if (r < Hh && c < Ww) t[threadIdx.y + j * 8][threadIdx.x] = s[r * Ww + c];
    }
    __syncthreads();
#pragma unroll
    for (int j = 0; j < 4; j++) {
        int r = c0 + threadIdx.y + j * 8, c = r0 + threadIdx.x;
        if (r < Ww && c < Hh) d[r * Hh + c] = t[threadIdx.x][threadIdx.y + j * 8];
    }
}

__global__ void t_bwd_kernel(float* __restrict__ dst) {         // tbuf -> buf
    __shared__ float t[32][33];
    size_t p = blockIdx.z;
    const float* s = g_tbuf + p * PLANE;
    float* d = dst + p * PLANE;
    int c0 = blockIdx.x * 32, r0 = blockIdx.y * 32;
#pragma unroll
    for (int j = 0; j < 4; j++) {
        int r = r0 + threadIdx.y + j * 8, c = c0 + threadIdx.x;
        if (r < Ww && c < Hh) t[threadIdx.y + j * 8][threadIdx.x] = s[r * Hh + c];
    }
    __syncthreads();
#pragma unroll
    for (int j = 0; j < 4; j++) {
        int r = c0 + threadIdx.y + j * 8, c = r0 + threadIdx.x;
        if (r < Hh && c < Ww) d[r * Ww + c] = t[threadIdx.x][threadIdx.y + j * 8];
    }
}

// ---------------------------------------------------------------------------
extern "C" void kernel_launch(void* const* d_in, const int* in_sizes, int n_in,
                              void* d_out, int out_size) {
    (void)in_sizes; (void)n_in; (void)out_size;
    float* buf = (float*)d_out;
    const size_t xbytes = (size_t)Bb * Cc * Hh * Ww * sizeof(float);

    cudaMemcpyAsync(buf, d_in[0], xbytes, cudaMemcpyDeviceToDevice);

    const int nw = Cc * Cc * Kk;
    for (int p = 0; p < 4; p++)
        transpose_w_kernel<<<(nw + 255) / 256, 256>>>((const float*)d_in[1 + p], p);

    const int vsmem = (Cc * Kk * COB + Cc * VSM_W) * (int)sizeof(float);  // 204800
    const int hsmem = (Cc * Kk * COB + Cc * HSM_W) * (int)sizeof(float);  // 172032
    cudaFuncSetAttribute((const void*)vpass_kernel,
                         cudaFuncAttributeMaxDynamicSharedMemorySize, vsmem);
    cudaFuncSetAttribute((const void*)hpass_kernel,
                         cudaFuncAttributeMaxDynamicSharedMemorySize, hsmem);

    dim3 grid(4, 32);
    vpass_kernel<<<grid, 224, vsmem>>>(buf, 0, +1);
    vpass_kernel<<<grid, 224, vsmem>>>(buf, 1, -1);

    { dim3 tb(32, 8), tg(4, 2, Bb * Cc); t_fwd_kernel<<<tg, tb>>>(buf); }

    hpass_kernel<<<grid, 160, hsmem>>>(2, +1);
    hpass_kernel<<<grid, 160, hsmem>>>(3, -1);

    { dim3 tb(32, 8), tg(2, 4, Bb * Cc); t_bwd_kernel<<<tg, tb>>>(buf); }
}

// round 16
// speedup vs baseline: 4.2371x; 1.0258x over previous
#include <cuda_runtime.h>

// SCNN message passing — persistent-per-pass, cluster-barrier + own-slice version.
// x: [B=32, C=128, H=36, W=100]; weights [128,128,9]; 4 passes of
// out[i] = x[i] + relu(conv1d(out[i-1])) scanned over H, H-rev, W, W-rev.
// Each pass = ONE kernel: grid (4 co-blocks, 32 b), cluster (4,1,1) = the 4
// co-blocks of one batch. Steps separated by barrier.cluster. Each CTA keeps
// its own 32-channel slice of the just-computed row in smem; staging reloads
// only the 96 peer channels through L2.

#define Bb 32
#define Cc 128
#define Hh 36
#define Ww 100
#define Kk 9
#define PLANE 3600

#define VSM_W 112     // vpass smem row stride: 4 halo + 100 + 8 pad
#define HSM_W 48      // hpass smem row stride: 4 halo + 36 + 8 pad
#define COB  32       // co per CTA

typedef unsigned long long ull;

// Transposed weights: [pass][ (ci*9 + k)*128 + co ]
__device__ float g_wT[4][Cc * Kk * Cc];
// Transposed feature scratch [B][C][W][H]
__device__ float g_tbuf[(size_t)Bb * Cc * Ww * Hh];

__device__ __forceinline__ ull pk2(float x) {
    ull r; asm("mov.b64 %0, {%1, %1};" : "=l"(r) : "f"(x)); return r;
}
__device__ __forceinline__ void fma2(ull& d, ull a, ull b) {
    asm("fma.rn.f32x2 %0, %1, %2, %0;" : "+l"(d) : "l"(a), "l"(b));
}
__device__ __forceinline__ float2 unpk(ull v) {
    float2 f; asm("mov.b64 {%0, %1}, %2;" : "=f"(f.x), "=f"(f.y) : "l"(v)); return f;
}

// Cluster-wide barrier: arrive(release) + wait(acquire) at cluster scope.
__device__ __forceinline__ void cluster_sync_rw() {
    asm volatile("barrier.cluster.arrive.aligned;" ::: "memory");
    asm volatile("barrier.cluster.wait.aligned;" ::: "memory");
}

// ---------------------------------------------------------------------------
__global__ void transpose_w_kernel(const float* __restrict__ src, int pass) {
    int idx = blockIdx.x * blockDim.x + threadIdx.x;
    if (idx >= Cc * Cc * Kk) return;
    int k  = idx % Kk;
    int ci = (idx / Kk) % Cc;
    int co = idx / (Kk * Cc);
    g_wT[pass][(ci * Kk + k) * Cc + co] = src[idx];
}

// ---------------------------------------------------------------------------
// Vertical pass (conv along W, scan over H), in place on buf [B,C,H,W].
// grid (4, 32), cluster (4,1,1); block 224 (200 compute: 25 wq x 8 cq).
// smem: wsm[128*9][32] (147456B) + srow[128][112] (57344B) = 204800B.
__global__ void __launch_bounds__(224) __cluster_dims__(4, 1, 1)
vpass_kernel(float* __restrict__ buf, int pass, int dir) {
    extern __shared__ float sm[];
    float* wsm  = sm;                       // [ (ci*9+k) ][32 co]
    float* srow = sm + Cc * Kk * COB;       // [128 ci][VSM_W]

    const int b   = blockIdx.y;
    const int co0 = blockIdx.x * COB;
    const int tid = threadIdx.x;

    // stage weights once: 9216 float4
    for (int i = tid; i < Cc * Kk * (COB / 4); i += 224) {
        int r = i / (COB / 4), q = (i % (COB / 4)) * 4;
        *(float4*)&wsm[r * COB + q] = *(const float4*)&g_wT[pass][r * Cc + co0 + q];
    }
    // halo zero
    for (int i = tid; i < Cc * 12; i += 224) {
        int ci = i / 12, j = i % 12;
        srow[ci * VSM_W + ((j < 4) ? j : (100 + j))] = 0.f;
    }
    __syncthreads();

    const int wq = tid % 25, cq = tid / 25;    // cq 0..7 valid
    const int w0 = wq * 4;
    const int co = co0 + cq * 4;

    for (int s = 0; s < Hh - 1; s++) {
        const int h_cur  = (dir > 0) ? (1 + s) : (Hh - 2 - s);
        const int h_prev = (dir > 0) ? s       : (Hh - 1 - s);

        // stage prev row; after step 0 our own 32 ci are already in srow
        const float* src = buf + (size_t)(b * Cc) * PLANE + (size_t)h_prev * Ww;
        if (s == 0) {
            for (int i = tid; i < Cc * 25; i += 224) {
                int ci = i / 25, q = i % 25;
                float4 v = __ldcg((const float4*)(src + (size_t)ci * PLANE + q * 4));
                *(float4*)&srow[ci * VSM_W + 4 + q * 4] = v;
            }
        } else {
            for (int i = tid; i < (Cc - COB) * 25; i += 224) {
                int cip = i / 25, q = i % 25;
                int ci = cip + ((cip >= co0) ? COB : 0);   // skip own slice
                float4 v = __ldcg((const float4*)(src + (size_t)ci * PLANE + q * 4));
                *(float4*)&srow[ci * VSM_W + 4 + q * 4] = v;
            }
        }
        __syncthreads();

        float4 p0, p1, p2, p3;
        if (tid < 200) {
            ull acc[8];                        // [w0..3][copair0..1]
#pragma unroll
            for (int j = 0; j < 8; j++) acc[j] = 0;

            for (int ci = 0; ci < Cc; ci++) {
                const float* r = &srow[ci * VSM_W + w0];
                float4 A = *(const float4*)(r);
                float4 B = *(const float4*)(r + 4);
                float4 C = *(const float4*)(r + 8);
                ull wv[12];
                wv[0] = pk2(A.x); wv[1] = pk2(A.y); wv[2]  = pk2(A.z); wv[3]  = pk2(A.w);
                wv[4] = pk2(B.x); wv[5] = pk2(B.y); wv[6]  = pk2(B.z); wv[7]  = pk2(B.w);
                wv[8] = pk2(C.x); wv[9] = pk2(C.y); wv[10] = pk2(C.z); wv[11] = pk2(C.w);

                const float* wb = &wsm[ci * (Kk * COB) + cq * 4];
#pragma unroll
                for (int k = 0; k < Kk; k++) {
                    ulonglong2 wt = *(const ulonglong2*)(wb + k * COB);
                    fma2(acc[0], wv[k + 0], wt.x); fma2(acc[1], wv[k + 0], wt.y);
                    fma2(acc[2], wv[k + 1], wt.x); fma2(acc[3], wv[k + 1], wt.y);
                    fma2(acc[4], wv[k + 2], wt.x); fma2(acc[5], wv[k + 2], wt.y);
                    fma2(acc[6], wv[k + 3], wt.x); fma2(acc[7], wv[k + 3], wt.y);
                }
            }

            // out[b][co + j][h_cur][w0..w0+3] += relu(acc)
            float2 u0 = unpk(acc[0]), u1 = unpk(acc[2]), u2 = unpk(acc[4]), u3 = unpk(acc[6]);
            float2 v0 = unpk(acc[1]), v1 = unpk(acc[3]), v2 = unpk(acc[5]), v3 = unpk(acc[7]);
            size_t base = ((size_t)(b * Cc + co) * Hh + h_cur) * Ww + w0;
            p0 = *(float4*)(buf + base);
            p0.x += fmaxf(u0.x, 0.f); p0.y += fmaxf(u1.x, 0.f);
            p0.z += fmaxf(u2.x, 0.f); p0.w += fmaxf(u3.x, 0.f);
            *(float4*)(buf + base) = p0;
            p1 = *(float4*)(buf + base + PLANE);
            p1.x += fmaxf(u0.y, 0.f); p1.y += fmaxf(u1.y, 0.f);
            p1.z += fmaxf(u2.y, 0.f); p1.w += fmaxf(u3.y, 0.f);
            *(float4*)(buf + base + PLANE) = p1;
            p2 = *(float4*)(buf + base + 2 * PLANE);
            p2.x += fmaxf(v0.x, 0.f); p2.y += fmaxf(v1.x, 0.f);
            p2.z += fmaxf(v2.x, 0.f); p2.w += fmaxf(v3.x, 0.f);
            *(float4*)(buf + base + 2 * PLANE) = p2;
            p3 = *(float4*)(buf + base + 3 * PLANE);
            p3.x += fmaxf(v0.y, 0.f); p3.y += fmaxf(v1.y, 0.f);
            p3.z += fmaxf(v2.y, 0.f); p3.w += fmaxf(v3.y, 0.f);
            *(float4*)(buf + base + 3 * PLANE) = p3;
        }

        if (s < Hh - 2) {
            __syncthreads();                  // all srow reads of this step done
            if (tid < 200) {                  // retain own slice for next step
                *(float4*)&srow[(co + 0) * VSM_W + 4 + w0] = p0;
                *(float4*)&srow[(co + 1) * VSM_W + 4 + w0] = p1;
                *(float4*)&srow[(co + 2) * VSM_W + 4 + w0] = p2;
                *(float4*)&srow[(co + 3) * VSM_W + 4 + w0] = p3;
            }
            cluster_sync_rw();
        }
    }
}

// ---------------------------------------------------------------------------
// Horizontal pass (conv along H, scan over W) on g_tbuf [B,C,W,H].
// grid (4, 32), cluster (4,1,1); block 160 (144 compute: 18 hq x 8 cq).
// smem: wsm 147456B + scol[128][48] 24576B = 172032B.
__global__ void __launch_bounds__(160) __cluster_dims__(4, 1, 1)
hpass_kernel(int pass, int dir) {
    extern __shared__ float sm[];
    float* wsm  = sm;
    float* scol = sm + Cc * Kk * COB;

    const int b   = blockIdx.y;
    const int co0 = blockIdx.x * COB;
    const int tid = threadIdx.x;
    float* tbuf = g_tbuf;

    for (int i = tid; i < Cc * Kk * (COB / 4); i += 160) {
        int r = i / (COB / 4), q = (i % (COB / 4)) * 4;
        *(float4*)&wsm[r * COB + q] = *(const float4*)&g_wT[pass][r * Cc + co0 + q];
    }
    for (int i = tid; i < Cc * 12; i += 160) {
        int ci = i / 12, j = i % 12;
        scol[ci * HSM_W + ((j < 4) ? j : (36 + j))] = 0.f;
    }
    __syncthreads();

    const int hq = tid % 18, cq = tid / 18;   // cq 0..7 valid
    const int h0 = hq * 2;
    const int co = co0 + cq * 4;

    for (int s = 0; s < Ww - 1; s++) {
        const int w_cur  = (dir > 0) ? (1 + s) : (Ww - 2 - s);
        const int w_prev = (dir > 0) ? s       : (Ww - 1 - s);

        const float* src = tbuf + (size_t)(b * Cc) * PLANE + (size_t)w_prev * Hh;
        if (s == 0) {
            for (int i = tid; i < Cc * 9; i += 160) {
                int ci = i / 9, q = i % 9;
                float4 v = __ldcg((const float4*)(src + (size_t)ci * PLANE + q * 4));
                *(float4*)&scol[ci * HSM_W + 4 + q * 4] = v;
            }
        } else {
            for (int i = tid; i < (Cc - COB) * 9; i += 160) {
                int cip = i / 9, q = i % 9;
                int ci = cip + ((cip >= co0) ? COB : 0);   // skip own slice
                float4 v = __ldcg((const float4*)(src + (size_t)ci * PLANE + q * 4));
                *(float4*)&scol[ci * HSM_W + 4 + q * 4] = v;
            }
        }
        __syncthreads();

        float2 q0, q1, q2, q3;
        if (tid < 144) {
            ull acc[4];                        // [h0,h1][copair0,1]
#pragma unroll
            for (int j = 0; j < 4; j++) acc[j] = 0;

            for (int ci = 0; ci < Cc; ci++) {
                const float* r = &scol[ci * HSM_W + h0];
                float2 d0 = *(const float2*)(r);
                float2 d1 = *(const float2*)(r + 2);
                float2 d2 = *(const float2*)(r + 4);
                float2 d3 = *(const float2*)(r + 6);
                float2 d4 = *(const float2*)(r + 8);
                ull wv[10];
                wv[0] = pk2(d0.x); wv[1] = pk2(d0.y);
                wv[2] = pk2(d1.x); wv[3] = pk2(d1.y);
                wv[4] = pk2(d2.x); wv[5] = pk2(d2.y);
                wv[6] = pk2(d3.x); wv[7] = pk2(d3.y);
                wv[8] = pk2(d4.x); wv[9] = pk2(d4.y);

                const float* wb = &wsm[ci * (Kk * COB) + cq * 4];
#pragma unroll
                for (int k = 0; k < Kk; k++) {
                    ulonglong2 wt = *(const ulonglong2*)(wb + k * COB);
                    fma2(acc[0], wv[k + 0], wt.x); fma2(acc[1], wv[k + 0], wt.y);
                    fma2(acc[2], wv[k + 1], wt.x); fma2(acc[3], wv[k + 1], wt.y);
                }
            }

            float2 a0 = unpk(acc[0]), a1 = unpk(acc[2]);   // (co+0,co+1)@h0 / @h1
            float2 b0 = unpk(acc[1]), b1 = unpk(acc[3]);   // (co+2,co+3)@h0 / @h1
            size_t base = ((size_t)(b * Cc + co) * Ww + w_cur) * Hh + h0;
            q0 = *(float2*)(tbuf + base);
            q0.x += fmaxf(a0.x, 0.f); q0.y += fmaxf(a1.x, 0.f);
            *(float2*)(tbuf + base) = q0;
            q1 = *(float2*)(tbuf + base + PLANE);
            q1.x += fmaxf(a0.y, 0.f); q1.y += fmaxf(a1.y, 0.f);
            *(float2*)(tbuf + base + PLANE) = q1;
            q2 = *(float2*)(tbuf + base + 2 * PLANE);
            q2.x += fmaxf(b0.x, 0.f); q2.y += fmaxf(b1.x, 0.f);
            *(float2*)(tbuf + base + 2 * PLANE) = q2;
            q3 = *(float2*)(tbuf + base + 3 * PLANE);
            q3.x += fmaxf(b0.y, 0.f); q3.y += fmaxf(b1.y, 0.f);
            *(float2*)(tbuf + base + 3 * PLANE) = q3;
        }

        if (s < Ww - 2) {
            __syncthreads();                  // all scol reads of this step done
            if (tid < 144) {                  // retain own slice for next step
                *(float2*)&scol[(co + 0) * HSM_W + 4 + h0] = q0;
                *(float2*)&scol[(co + 1) * HSM_W + 4 + h0] = q1;
                *(float2*)&scol[(co + 2) * HSM_W + 4 + h0] = q2;
                *(float2*)&scol[(co + 3) * HSM_W + 4 + h0] = q3;
            }
            cluster_sync_rw();
        }
    }
}

// ---------------------------------------------------------------------------
__global__ void t_fwd_kernel(const float* __restrict__ src) {   // buf -> tbuf
    __shared__ float t[32][33];
    size_t p = blockIdx.z;
    const float* s = src + p * PLANE;
    float* d = g_tbuf + p * PLANE;
    int c0 = blockIdx.x * 32, r0 = blockIdx.y * 32;
#pragma unroll
    for (int j = 0; j < 4; j++) {
        int r = r0 + threadIdx.y + j * 8, c = c0 + threadIdx.x;
        if (r < Hh && c < Ww) t[threadIdx.y + j * 8][threadIdx.x] = s[r * Ww + c];
    }
    __syncthreads();
#pragma unroll
    for (int j = 0; j < 4; j++) {
        int r = c0 + threadIdx.y + j * 8, c = r0 + threadIdx.x;
        if (r < Ww && c < Hh) d[r * Hh + c] = t[threadIdx.x][threadIdx.y + j * 8];
    }
}

__global__ void t_bwd_kernel(float* __restrict__ dst) {         // tbuf -> buf
    __shared__ float t[32][33];
    size_t p = blockIdx.z;
    const float* s = g_tbuf + p * PLANE;
    float* d = dst + p * PLANE;
    int c0 = blockIdx.x * 32, r0 = blockIdx.y * 32;
#pragma unroll
    for (int j = 0; j < 4; j++) {
        int r = r0 + threadIdx.y + j * 8, c = c0 + threadIdx.x;
        if (r < Ww && c < Hh) t[threadIdx.y + j * 8][threadIdx.x] = s[r * Hh + c];
    }
    __syncthreads();
#pragma unroll
    for (int j = 0; j < 4; j++) {
        int r = c0 + threadIdx.y + j * 8, c = r0 + threadIdx.x;
        if (r < Hh && c < Ww) d[r * Ww + c] = t[threadIdx.x][threadIdx.y + j * 8];
    }
}

// ---------------------------------------------------------------------------
extern "C" void kernel_launch(void* const* d_in, const int* in_sizes, int n_in,
                              void* d_out, int out_size) {
    (void)in_sizes; (void)n_in; (void)out_size;
    float* buf = (float*)d_out;
    const size_t xbytes = (size_t)Bb * Cc * Hh * Ww * sizeof(float);

    cudaMemcpyAsync(buf, d_in[0], xbytes, cudaMemcpyDeviceToDevice);

    const int nw = Cc * Cc * Kk;
    for (int p = 0; p < 4; p++)
        transpose_w_kernel<<<(nw + 255) / 256, 256>>>((const float*)d_in[1 + p], p);

    const int vsmem = (Cc * Kk * COB + Cc * VSM_W) * (int)sizeof(float);  // 204800
    const int hsmem = (Cc * Kk * COB + Cc * HSM_W) * (int)sizeof(float);  // 172032
    cudaFuncSetAttribute((const void*)vpass_kernel,
                         cudaFuncAttributeMaxDynamicSharedMemorySize, vsmem);
    cudaFuncSetAttribute((const void*)hpass_kernel,
                         cudaFuncAttributeMaxDynamicSharedMemorySize, hsmem);

    dim3 grid(4, 32);
    vpass_kernel<<<grid, 224, vsmem>>>(buf, 0, +1);
    vpass_kernel<<<grid, 224, vsmem>>>(buf, 1, -1);

    { dim3 tb(32, 8), tg(4, 2, Bb * Cc); t_fwd_kernel<<<tg, tb>>>(buf); }

    hpass_kernel<<<grid, 160, hsmem>>>(2, +1);
    hpass_kernel<<<grid, 160, hsmem>>>(3, -1);

    { dim3 tb(32, 8), tg(2, 4, Bb * Cc); t_bwd_kernel<<<tg, tb>>>(buf); }
}